// round 1
// baseline (speedup 1.0000x reference)
#include <cuda_runtime.h>
#include <stdint.h>

// Problem shape (fixed by the reference): x is (T, B, 1) fp32, lr scalar.
#define T_DIM 8192
#define B_DIM 4096
#define S_CHUNKS 64
#define CH 128          // T_DIM / S_CHUNKS
#define NWORDS 4        // CH / 32

// Scratch (device globals — no allocation allowed in kernel_launch).
// Layout is chunk-major so every access is coalesced over b.
__device__ float4 g_coef [S_CHUNKS * B_DIM];  // (A0, C0, A1, C1) per (s,b)   4 MB
__device__ uint4  g_bits [S_CHUNKS * B_DIM];  // 128 packed x bits per (s,b)  4 MB
__device__ float  g_xprev[S_CHUNKS * B_DIM];  // x[t0-1] per (s,b)            1 MB
__device__ float2 g_state[S_CHUNKS * B_DIM];  // (p0,p1) entering chunk       2 MB

__device__ __forceinline__ float clamp_lr(const float* lrp) {
    float lr = *lrp;
    return fminf(fmaxf(lr, 0.0f), 1.0f);
}

// ---------------------------------------------------------------------------
// Pass 1: per (chunk s, column b) — read x chunk once, emit:
//   - packed bits of x_t
//   - affine composition (A0,C0,A1,C1) of the chunk's effect on (p0,p1)
//   - x value immediately preceding the chunk (obs_prev seed)
// Step semantics: using xprev = x_{t-1} (x_{-1} = 0):
//   if xprev==0: p0 <- (1-lr)*p0 + lr*x_t   (p1 unchanged)
//   else       : p1 <- (1-lr)*p1 + lr*x_t   (p0 unchanged)
// ---------------------------------------------------------------------------
__global__ void __launch_bounds__(256) pass1_kernel(
    const float* __restrict__ x, const float* __restrict__ lrp)
{
    const int b = blockIdx.x * blockDim.x + threadIdx.x;
    const int s = blockIdx.y;
    const float lr = clamp_lr(lrp);
    const float r  = 1.0f - lr;

    const int t0 = s * CH;
    const float* xp = x + (size_t)t0 * B_DIM + b;

    float xprev = (s == 0) ? 0.0f : xp[-(ptrdiff_t)B_DIM];
    g_xprev[s * B_DIM + b] = xprev;
    bool pb = (xprev != 0.0f);

    float A0 = 1.0f, C0 = 0.0f, A1 = 1.0f, C1 = 0.0f;
    uint32_t words[NWORDS];

    #pragma unroll
    for (int wi = 0; wi < NWORDS; wi++) {
        uint32_t w = 0;
        // Unroll-by-8 so ptxas batches 8 independent LDGs per group (MLP).
        #pragma unroll
        for (int i0 = 0; i0 < 32; i0 += 8) {
            float xv[8];
            #pragma unroll
            for (int j = 0; j < 8; j++)
                xv[j] = xp[(size_t)(wi * 32 + i0 + j) * B_DIM];
            #pragma unroll
            for (int j = 0; j < 8; j++) {
                const float xj = xv[j];
                const bool  xb = (xj != 0.0f);
                // multipliers / addends for this step (exact selects, x in {0,1})
                const float m0 = pb ? 1.0f : r;
                const float m1 = pb ? r    : 1.0f;
                const float a0 = (!pb && xb) ? lr : 0.0f;
                const float a1 = ( pb && xb) ? lr : 0.0f;
                A0 *= m0;  C0 = fmaf(C0, m0, a0);
                A1 *= m1;  C1 = fmaf(C1, m1, a1);
                // shift-insert: after 32 steps, step k's bit sits at position k
                w = (w >> 1) | (xb ? 0x80000000u : 0u);
                pb = xb;
            }
        }
        words[wi] = w;
    }

    g_coef[s * B_DIM + b] = make_float4(A0, C0, A1, C1);
    g_bits[s * B_DIM + b] = make_uint4(words[0], words[1], words[2], words[3]);
}

// ---------------------------------------------------------------------------
// Scan: one thread per column; 64 sequential affine compositions.
// Stores the (p0,p1) state entering each chunk.
// ---------------------------------------------------------------------------
__global__ void __launch_bounds__(256) scan_kernel()
{
    const int b = blockIdx.x * blockDim.x + threadIdx.x;
    float p0 = 0.5f, p1 = 0.5f;
    #pragma unroll 8
    for (int s = 0; s < S_CHUNKS; s++) {
        const float4 c = g_coef[s * B_DIM + b];
        g_state[s * B_DIM + b] = make_float2(p0, p1);
        p0 = fmaf(p0, c.x, c.y);
        p1 = fmaf(p1, c.z, c.w);
    }
}

// ---------------------------------------------------------------------------
// Pass 2: replay each chunk from its stored entry state using the packed bits
// (no re-read of x from HBM). Writes preds. The per-step math mirrors the
// reference exactly given binary x: fmaf(0,d,p)==p, select(x,p1,p0) exact.
// ---------------------------------------------------------------------------
__global__ void __launch_bounds__(256) pass2_kernel(
    float* __restrict__ out, const float* __restrict__ lrp)
{
    const int b = blockIdx.x * blockDim.x + threadIdx.x;
    const int s = blockIdx.y;
    const float lr = clamp_lr(lrp);

    const int t0 = s * CH;
    float* op = out + (size_t)t0 * B_DIM + b;

    const float2 st = g_state[s * B_DIM + b];
    float p0 = st.x, p1 = st.y;
    const uint4 bw = g_bits[s * B_DIM + b];
    uint32_t words[NWORDS] = { bw.x, bw.y, bw.z, bw.w };
    bool pb = (g_xprev[s * B_DIM + b] != 0.0f);

    #pragma unroll
    for (int wi = 0; wi < NWORDS; wi++) {
        uint32_t w = words[wi];
        #pragma unroll
        for (int i = 0; i < 32; i++) {
            const bool  xb = (w & 1u);
            w >>= 1;
            const float xv = xb ? 1.0f : 0.0f;
            const float l0 = pb ? 0.0f : lr;
            const float l1 = pb ? lr   : 0.0f;
            p0 = fmaf(l0, xv - p0, p0);
            p1 = fmaf(l1, xv - p1, p1);
            op[(size_t)(wi * 32 + i) * B_DIM] = xb ? p1 : p0;
            pb = xb;
        }
    }
}

extern "C" void kernel_launch(void* const* d_in, const int* in_sizes, int n_in,
                              void* d_out, int out_size)
{
    // metadata order: x (T*B floats), lr (1 float). Be defensive about order.
    const float* x  = (const float*)d_in[0];
    const float* lr = (const float*)d_in[1];
    if (n_in >= 2 && in_sizes[0] == 1) { x = (const float*)d_in[1]; lr = (const float*)d_in[0]; }
    float* out = (float*)d_out;

    dim3 blk(256);
    dim3 grid_pass(B_DIM / 256, S_CHUNKS);

    pass1_kernel<<<grid_pass, blk>>>(x, lr);
    scan_kernel<<<B_DIM / 256, blk>>>();
    pass2_kernel<<<grid_pass, blk>>>(out, lr);
}